// round 3
// baseline (speedup 1.0000x reference)
#include <cuda_runtime.h>

// graphDenoising: per-(b,n) rank-1 bilinear scores + sigmoid.
// DRAM-roofline stream (1.61 GB). Software-pipelined: each warp owns
// ROWS_PER_WARP consecutive rows; next row's 6 LDG.128 are issued before
// the current row's shuffle-reduce, so memory pressure never drops.

#define DIM 256
#define ROWS_PER_WARP 8
#define THREADS 256

__device__ __forceinline__ float dot8(float4 a0, float4 a1, float4 w0, float4 w1)
{
    float d = a0.x * w0.x;
    d = fmaf(a0.y, w0.y, d); d = fmaf(a0.z, w0.z, d); d = fmaf(a0.w, w0.w, d);
    d = fmaf(a1.x, w1.x, d); d = fmaf(a1.y, w1.y, d);
    d = fmaf(a1.z, w1.z, d); d = fmaf(a1.w, w1.w, d);
    return d;
}

__global__ __launch_bounds__(THREADS)
void graph_denoise_kernel(const float* __restrict__ user_emb,
                          const float* __restrict__ pos_emb,
                          const float* __restrict__ neg_emb,
                          const float* __restrict__ beh_emb,
                          const float* __restrict__ prompt_emb,
                          float* __restrict__ out,
                          int N, int B)
{
    const int warp_id = (blockIdx.x * blockDim.x + threadIdx.x) >> 5;
    const int lane = threadIdx.x & 31;
    const int total = B * N;

    const int row_start = warp_id * ROWS_PER_WARP;
    if (row_start >= total) return;

    // N % ROWS_PER_WARP == 0, so the whole chunk shares one behavior.
    const int b = row_start / N;
    const int n_start = row_start - b * N;

    const float4* w4 = (b < B - 1)
        ? reinterpret_cast<const float4*>(beh_emb + (size_t)b * DIM)
        : reinterpret_cast<const float4*>(prompt_emb);
    const float4 w0 = w4[lane];
    const float4 w1 = w4[lane + 32];

    float* ob = out + (size_t)b * 2 * N;

    // Prime the pipeline: loads for row 0 of the chunk.
    size_t base = (size_t)row_start * DIM;
    const float4* u4 = reinterpret_cast<const float4*>(user_emb + base);
    const float4* p4 = reinterpret_cast<const float4*>(pos_emb  + base);
    const float4* g4 = reinterpret_cast<const float4*>(neg_emb  + base);

    float4 a0 = u4[lane], a1 = u4[lane + 32];
    float4 b0 = p4[lane], b1 = p4[lane + 32];
    float4 c0 = g4[lane], c1 = g4[lane + 32];

    #pragma unroll
    for (int i = 0; i < ROWS_PER_WARP; i++) {
        // Prefetch next row (independent of current compute; ptxas hoists
        // these 6 LDG.128 above the shuffle chain below).
        float4 na0, na1, nb0, nb1, nc0, nc1;
        if (i + 1 < ROWS_PER_WARP) {
            const size_t nbase = (size_t)(row_start + i + 1) * DIM;
            const float4* nu = reinterpret_cast<const float4*>(user_emb + nbase);
            const float4* np = reinterpret_cast<const float4*>(pos_emb  + nbase);
            const float4* ng = reinterpret_cast<const float4*>(neg_emb  + nbase);
            na0 = nu[lane]; na1 = nu[lane + 32];
            nb0 = np[lane]; nb1 = np[lane + 32];
            nc0 = ng[lane]; nc1 = ng[lane + 32];
        }

        float du = dot8(a0, a1, w0, w1);
        float dp = dot8(b0, b1, w0, w1);
        float dg = dot8(c0, c1, w0, w1);

        #pragma unroll
        for (int off = 16; off > 0; off >>= 1) {
            du += __shfl_xor_sync(0xffffffffu, du, off);
            dp += __shfl_xor_sync(0xffffffffu, dp, off);
            dg += __shfl_xor_sync(0xffffffffu, dg, off);
        }

        if (lane == 0) {
            const int n = n_start + i;
            ob[n]     = 1.0f / (1.0f + __expf(-(du * dp)));
            ob[N + n] = 1.0f / (1.0f + __expf(-(du * dg)));
        }

        if (i + 1 < ROWS_PER_WARP) {
            a0 = na0; a1 = na1;
            b0 = nb0; b1 = nb1;
            c0 = nc0; c1 = nc1;
        }
    }
}

extern "C" void kernel_launch(void* const* d_in, const int* in_sizes, int n_in,
                              void* d_out, int out_size)
{
    const float* user_emb   = (const float*)d_in[0];
    const float* pos_emb    = (const float*)d_in[1];
    const float* neg_emb    = (const float*)d_in[2];
    const float* beh_emb    = (const float*)d_in[3];
    const float* prompt_emb = (const float*)d_in[4];
    float* out = (float*)d_out;

    const int B = in_sizes[3] / DIM;            // 4
    const int N = in_sizes[0] / (B * DIM);      // 131072

    const int total_rows = B * N;               // 524288
    const int warps_per_block = THREADS / 32;
    const int rows_per_block = warps_per_block * ROWS_PER_WARP;
    const int blocks = (total_rows + rows_per_block - 1) / rows_per_block;  // 8192

    graph_denoise_kernel<<<blocks, THREADS>>>(user_emb, pos_emb, neg_emb,
                                              beh_emb, prompt_emb, out, N, B);
}